// round 8
// baseline (speedup 1.0000x reference)
#include <cuda_runtime.h>
#include <cstdint>

// Problem constants
#define BDIM 64
#define ICC  128
#define OCC  128
#define OD   1024          // out_dim; L = 2*OD
#define KC   16            // ic chunk held in smem
#define DT   2             // d's per block
#define OCT  64            // o's per block

using ull = unsigned long long;

// Packed 2xFP32 FMA: d.lo += a.lo*b.lo ; d.hi += a.hi*b.hi  (FFMA2, sm_100+)
#define FMA_F32X2(d_, a_, b_) \
  asm("fma.rn.f32x2 %0, %1, %2, %0;" : "+l"(d_) : "l"(a_), "l"(b_))

__global__ void __launch_bounds__(256, 2)
nolc1d_kernel(const float2* __restrict__ X2,   // x viewed as (B, IC, OD) float2
              const float2* __restrict__ W2,   // w viewed as (OC, IC, OD) float2
              float* __restrict__ out)         // (B, OC, OD)
{
    __shared__ __align__(16) float2 Xs[KC][DT][BDIM];  // 16 KB
    __shared__ __align__(16) float2 Ws[KC][DT][OCT];   // 16 KB

    const int tid = threadIdx.x;
    const int d0  = blockIdx.x * DT;       // 0..1022 step 2
    const int oc0 = blockIdx.y * OCT;      // 0 or 64

    // compute-side decomposition: dg selects the d slice, 128 threads per slice
    const int dg = tid >> 7;               // 0..1
    const int t  = tid & 127;
    const int ty = t >> 4;                 // 0..7  -> 8 b-rows each
    const int tx = t & 15;                 // 0..15 -> 4 o-cols each
    const int b0 = ty * 8;
    const int ol = tx * 4;

    // loader decomposition: row r = tid + i*256 -> k = lk + 4*i, col = lc
    const int lk = tid >> 6;               // 0..3
    const int lc = tid & 63;               // b (for X) / local o (for W)

    const float2* xbase = X2 + (size_t)lc * (ICC * OD) + d0;
    const float2* wbase = W2 + (size_t)(oc0 + lc) * (ICC * OD) + d0;

    ull acc[8][4];
    #pragma unroll
    for (int i = 0; i < 8; ++i)
        #pragma unroll
        for (int j = 0; j < 4; ++j)
            acc[i][j] = 0ull;   // two packed +0.0f

    for (int kc = 0; kc < ICC; kc += KC) {
        // ---- global -> smem: each thread loads 4 rows of X and 4 of W,
        // each row = float4 = the (d0, d0+1) pair-of-pairs for one (col, ic).
        #pragma unroll
        for (int i = 0; i < 4; ++i) {
            const int k = lk + i * 4;
            float4 gx = *reinterpret_cast<const float4*>(xbase + (size_t)(kc + k) * OD);
            Xs[k][0][lc] = make_float2(gx.x, gx.y);
            Xs[k][1][lc] = make_float2(gx.z, gx.w);
            float4 gw = *reinterpret_cast<const float4*>(wbase + (size_t)(kc + k) * OD);
            Ws[k][0][lc] = make_float2(gw.x, gw.y);
            Ws[k][1][lc] = make_float2(gw.z, gw.w);
        }
        __syncthreads();

        // ---- compute: 16 k-steps; per step, hold 4 w-frags and stream
        // x-frags 4 at a time (keeps live frag regs at 16 -> 2 CTAs/SM).
        #pragma unroll
        for (int k = 0; k < KC; ++k) {
            ull wv[4];
            {
                const ulonglong2* wp =
                    reinterpret_cast<const ulonglong2*>(&Ws[k][dg][ol]);
                ulonglong2 w0 = wp[0], w1 = wp[1];
                wv[0] = w0.x; wv[1] = w0.y; wv[2] = w1.x; wv[3] = w1.y;
            }
            const ulonglong2* xp =
                reinterpret_cast<const ulonglong2*>(&Xs[k][dg][b0]);

            #pragma unroll
            for (int h = 0; h < 2; ++h) {
                ull xv[4];
                ulonglong2 a0 = xp[2 * h + 0], a1 = xp[2 * h + 1];
                xv[0] = a0.x; xv[1] = a0.y; xv[2] = a1.x; xv[3] = a1.y;

                #pragma unroll
                for (int bb = 0; bb < 4; ++bb)
                    #pragma unroll
                    for (int oo = 0; oo < 4; ++oo)
                        FMA_F32X2(acc[4 * h + bb][oo], xv[bb], wv[oo]);
            }
        }
        __syncthreads();
    }

    // ---- epilogue: out = (lo + hi) / sqrt(IC)
    const float scale = 0.08838834764831843f;  // 1/sqrt(128)
    const int dcol = d0 + dg;
    #pragma unroll
    for (int bb = 0; bb < 8; ++bb) {
        const int b = b0 + bb;
        #pragma unroll
        for (int oo = 0; oo < 4; ++oo) {
            const int o = oc0 + ol + oo;
            float2 v = *reinterpret_cast<float2*>(&acc[bb][oo]);
            out[((size_t)b * OCC + o) * OD + dcol] = (v.x + v.y) * scale;
        }
    }
}

extern "C" void kernel_launch(void* const* d_in, const int* in_sizes, int n_in,
                              void* d_out, int out_size)
{
    // x: (64,128,2048) = 16,777,216 floats ; weight: (128,128,2048) = 33,554,432
    const void* xa = d_in[0];
    const void* wa = d_in[1];
    if (n_in >= 2 && in_sizes[0] == OCC * ICC * 2 * OD &&
        in_sizes[1] == BDIM * ICC * 2 * OD) {
        const void* tmp = xa; xa = wa; wa = tmp;  // defensive: order swapped
    }
    const float2* x = reinterpret_cast<const float2*>(xa);
    const float2* w = reinterpret_cast<const float2*>(wa);
    float* out = reinterpret_cast<float*>(d_out);

    dim3 grid(OD / DT, OCC / OCT);   // (512, 2)
    nolc1d_kernel<<<grid, 256>>>(x, w, out);
}

// round 11
// speedup vs baseline: 1.2570x; 1.2570x over previous
#include <cuda_runtime.h>
#include <cstdint>

#define ICC 128
#define OCC 128
#define BDIM 64
#define OD  1024
#define LL  2048
#define KC  8            // ic per chunk
#define DT  8            // d per block
#define OT  32           // o per block
#define XROW 66          // float2 per dd-row (64 + 2 pad)
#define WROW 34          // 32 + 2 pad
#define XS_B (KC*DT*XROW*8)          // 33792
#define WS_B (KC*DT*WROW*8)          // 17408
#define BUF_B (XS_B + WS_B)          // 51200
#define SMEM_B (2*BUF_B)             // 102400

using ull = unsigned long long;
#define FMA_F32X2(d_, a_, b_) \
  asm("fma.rn.f32x2 %0, %1, %2, %0;" : "+l"(d_) : "l"(a_), "l"(b_))

__global__ void __launch_bounds__(512, 1)
nolc8(const float* __restrict__ X, const float* __restrict__ W,
      float* __restrict__ out)
{
    extern __shared__ __align__(16) char sm[];
    const int tid = threadIdx.x;
    const int oc0 = blockIdx.x * OT;       // 0,32,64,96
    const int d0  = blockIdx.y * DT;
    const int l0  = d0 * 2;
    const size_t RS = (size_t)ICC * LL;

    // compute map
    const int dg = tid >> 6;               // 0..7
    const int ty = (tid >> 3) & 7;         // 8 b's
    const int tx = tid & 7;                // 4 o's

    // loader map: lanes along l
    const int jj = tid & 3;                // float4 within 64B row
    const int rr = tid >> 2;               // 0..127

    float4 px[4], pw[2];
    ull acc[8][4];
    #pragma unroll
    for (int i = 0; i < 8; ++i)
        #pragma unroll
        for (int j = 0; j < 4; ++j) acc[i][j] = 0ull;

    auto LDG = [&](int c) {
        const int ic0 = c * KC;
        #pragma unroll
        for (int p = 0; p < 4; ++p) {
            int r = rr + 128 * p, b = r & 63, ic = r >> 6;
            px[p] = *reinterpret_cast<const float4*>(
                X + (size_t)b * RS + (size_t)(ic0 + ic) * LL + l0 + 4 * jj);
        }
        #pragma unroll
        for (int p = 0; p < 2; ++p) {
            int r = rr + 128 * p, o = r & 31, ic = r >> 5;
            pw[p] = *reinterpret_cast<const float4*>(
                W + (size_t)(oc0 + o) * RS + (size_t)(ic0 + ic) * LL + l0 + 4 * jj);
        }
    };
    auto STS = [&](int buf) {
        float2* xs = reinterpret_cast<float2*>(sm + buf * BUF_B);
        float2* ws = reinterpret_cast<float2*>(sm + buf * BUF_B + XS_B);
        #pragma unroll
        for (int p = 0; p < 4; ++p) {
            int r = rr + 128 * p, b = r & 63, ic = r >> 6;
            xs[(ic * DT + 2 * jj) * XROW + b]     = make_float2(px[p].x, px[p].y);
            xs[(ic * DT + 2 * jj + 1) * XROW + b] = make_float2(px[p].z, px[p].w);
        }
        #pragma unroll
        for (int p = 0; p < 2; ++p) {
            int r = rr + 128 * p, o = r & 31, ic = r >> 5;
            ws[(ic * DT + 2 * jj) * WROW + o]     = make_float2(pw[p].x, pw[p].y);
            ws[(ic * DT + 2 * jj + 1) * WROW + o] = make_float2(pw[p].z, pw[p].w);
        }
    };

    LDG(0);
    STS(0);
    __syncthreads();

    int buf = 0;
    for (int c = 0; c < ICC / KC; ++c) {
        if (c + 1 < ICC / KC) LDG(c + 1);

        const char* xb = sm + buf * BUF_B + (size_t)dg * (XROW * 8) + ty * 64;
        const char* wb = sm + buf * BUF_B + XS_B + (size_t)dg * (WROW * 8) + tx * 32;
        #pragma unroll
        for (int k = 0; k < KC; ++k) {
            const ulonglong2* xp = reinterpret_cast<const ulonglong2*>(
                xb + (size_t)k * (DT * XROW * 8));
            const ulonglong2* wp = reinterpret_cast<const ulonglong2*>(
                wb + (size_t)k * (DT * WROW * 8));
            ulonglong2 w01 = wp[0], w23 = wp[1];
            ull wv[4] = { w01.x, w01.y, w23.x, w23.y };
            ulonglong2 a0 = xp[0], a1 = xp[1], a2 = xp[2], a3 = xp[3];
            ull xv[8] = { a0.x, a0.y, a1.x, a1.y, a2.x, a2.y, a3.x, a3.y };
            #pragma unroll
            for (int bb = 0; bb < 8; ++bb)
                #pragma unroll
                for (int oo = 0; oo < 4; ++oo)
                    FMA_F32X2(acc[bb][oo], xv[bb], wv[oo]);
        }

        if (c + 1 < ICC / KC) STS(buf ^ 1);
        __syncthreads();
        buf ^= 1;
    }

    // ---- epilogue through smem: 32B contiguous d-runs out ----
    const float scale = 0.08838834764831843f;  // 1/sqrt(128)
    float* eb = reinterpret_cast<float*>(sm);  // Ebuf[64][32][12]
    #pragma unroll
    for (int bb = 0; bb < 8; ++bb)
        #pragma unroll
        for (int oo = 0; oo < 4; ++oo) {
            float2 v = *reinterpret_cast<float2*>(&acc[bb][oo]);
            eb[((8 * ty + bb) * OT + 4 * tx + oo) * 12 + dg] = (v.x + v.y) * scale;
        }
    __syncthreads();
    #pragma unroll
    for (int i = 0; i < 8; ++i) {
        int s = i * 512 + tid;
        int j = s & 1, row = s >> 1;           // row = b*32 + o
        int b = row >> 5, o = row & 31;
        float4 v = *reinterpret_cast<const float4*>(eb + row * 12 + 4 * j);
        *reinterpret_cast<float4*>(
            out + ((size_t)b * OCC + oc0 + o) * OD + d0 + 4 * j) = v;
    }
}

extern "C" void kernel_launch(void* const* d_in, const int* in_sizes, int n_in,
                              void* d_out, int out_size)
{
    const void* xa = d_in[0];
    const void* wa = d_in[1];
    if (n_in >= 2 && in_sizes[0] == OCC * ICC * LL &&
        in_sizes[1] == BDIM * ICC * LL) {
        const void* t = xa; xa = wa; wa = t;   // defensive: order swapped
    }
    cudaFuncSetAttribute(nolc8, cudaFuncAttributeMaxDynamicSharedMemorySize,
                         SMEM_B);
    dim3 grid(OCC / OT, OD / DT);              // (4, 128), oc fastest
    nolc8<<<grid, 512, SMEM_B>>>(reinterpret_cast<const float*>(xa),
                                 reinterpret_cast<const float*>(wa),
                                 reinterpret_cast<float*>(d_out));
}